// round 3
// baseline (speedup 1.0000x reference)
#include <cuda_runtime.h>
#include <cuda_fp16.h>

typedef unsigned long long ull;

#define Bn 16
#define Fn 257
#define FPAD 272          // Fn padded to multiple of 16 (zeros)
#define Tn 8000
#define NBn 64
#define CHUNK 400
#define NCH 20
#define WARM 256
#define TTILE 128
#define FB_LD 64

#define SMEM2 ((FPAD * TTILE + FPAD * FB_LD) * (int)sizeof(__half))  // 104448

// 65.8 MB fp16 scratch for 0.1*vnr (device global: allocation-free)
__device__ __align__(128) __half g_vnr[(size_t)Bn * Fn * Tn];

struct __align__(8) H4 { __half2 a, b; };

// ---------------- packed f32x2 helpers ----------------
__device__ __forceinline__ ull f2pack(float lo, float hi) {
    ull r; asm("mov.b64 %0, {%1, %2};" : "=l"(r) : "f"(lo), "f"(hi)); return r;
}
__device__ __forceinline__ ull f2add(ull a, ull b) {
    ull d; asm("add.rn.f32x2 %0, %1, %2;" : "=l"(d) : "l"(a), "l"(b)); return d;
}
__device__ __forceinline__ void f2unpack(ull v, float& lo, float& hi) {
    asm("mov.b64 {%0, %1}, %2;" : "=f"(lo), "=f"(hi) : "l"(v));
}

// ---------------- branch-free contractive EMA step ----------------
__device__ __forceinline__ float nf_step(float x, float nf, float rise, float fall, float fl) {
    float d  = x - nf;
    float cr = fmaf(rise, d, nf);
    float cf = fmaf(fall, d, nf);
    return fmaxf(fmaxf(cr, cf), fl);
}

// ============================================================
// K1: chunked noise-floor scan -> fp16 scratch (0.1 * vnr)
// ============================================================
__global__ __launch_bounds__(256) void scan_kernel(
    const float* __restrict__ mag,
    const float* __restrict__ p_ns,
    const float* __restrict__ p_rr,
    const float* __restrict__ p_rf)
{
    int tid = blockIdx.x * 256 + threadIdx.x;
    if (tid >= Bn * Fn * NCH) return;
    int chunk = tid % NCH;
    int chain = tid / NCH;

    float rise = 1.0f / (1.0f + expf(-__ldg(p_rr)));
    float fall = 1.0f / (1.0f + expf(-__ldg(p_rf)));
    float ns   = fabsf(__ldg(p_ns));

    size_t base = (size_t)chain * Tn;
    const float4* gm = reinterpret_cast<const float4*>(mag + base);
    H4* gv = reinterpret_cast<H4*>(g_vnr + base);

    float mn = 3.4e38f;
    #pragma unroll
    for (int i = 0; i < 20; ++i) mn = fminf(mn, __ldg(mag + base + i));
    mn = fmaxf(mn, 1e-5f);
    const float fl = 0.5f * mn;
    float nf = mn;

    int t0 = chunk * CHUNK;
    int tw = (chunk == 0) ? 0 : (t0 - WARM);

    for (int q = (tw >> 2); q < (t0 >> 2); ++q) {
        float4 v = gm[q];
        nf = nf_step(v.x, nf, rise, fall, fl);
        nf = nf_step(v.y, nf, rise, fall, fl);
        nf = nf_step(v.z, nf, rise, fall, fl);
        nf = nf_step(v.w, nf, rise, fall, fl);
    }

    const int q0 = t0 >> 2;
    float4 b0 = gm[q0], b1 = gm[q0 + 1], b2 = gm[q0 + 2], b3 = gm[q0 + 3];

    #define EMIT4(c, idx) { \
        float o0, o1, o2, o3; \
        nf = nf_step(c.x, nf, rise, fall, fl); o0 = __fdividef(c.x, fmaf(ns, nf, 1e-8f)) * 0.1f; \
        nf = nf_step(c.y, nf, rise, fall, fl); o1 = __fdividef(c.y, fmaf(ns, nf, 1e-8f)) * 0.1f; \
        nf = nf_step(c.z, nf, rise, fall, fl); o2 = __fdividef(c.z, fmaf(ns, nf, 1e-8f)) * 0.1f; \
        nf = nf_step(c.w, nf, rise, fall, fl); o3 = __fdividef(c.w, fmaf(ns, nf, 1e-8f)) * 0.1f; \
        H4 st; st.a = __floats2half2_rn(o0, o1); st.b = __floats2half2_rn(o2, o3); \
        gv[idx] = st; }

    for (int i = 0; i < CHUNK / 4; i += 4) {
        float4 c0 = b0, c1 = b1, c2 = b2, c3 = b3;
        if (i + 8 <= CHUNK / 4) {
            b0 = gm[q0 + i + 4]; b1 = gm[q0 + i + 5];
            b2 = gm[q0 + i + 6]; b3 = gm[q0 + i + 7];
        }
        EMIT4(c0, q0 + i);
        EMIT4(c1, q0 + i + 1);
        EMIT4(c2, q0 + i + 2);
        EMIT4(c3, q0 + i + 3);
    }
    #undef EMIT4
}

// ============================================================
// K2: band GEMM + tanh. All-fp16 smem tiles (104KB -> 2 blocks/SM).
// HFMA2 inner product, fp16 accumulate per 16-f chunk, f32x2 master accs.
// Thread tile: 8 bands x 4 t.
// ============================================================
extern __shared__ __half k2_smem[];

__global__ __launch_bounds__(256, 2) void band_kernel(
    const float* __restrict__ fb, float* __restrict__ out)
{
    __half* vs = k2_smem;                    // [FPAD][TTILE]
    __half* fs = k2_smem + FPAD * TTILE;     // [FPAD][FB_LD] : fs[f*64 + n]
    const int b  = blockIdx.y;
    const int t0 = blockIdx.x * TTILE;
    const int tid = threadIdx.x;

    // fb transpose into fp16 smem (zeros for f >= Fn)
    for (int i = tid; i < NBn * FPAD; i += 256) {
        int n = i / FPAD;
        int f = i - n * FPAD;
        float w = (f < Fn) ? __ldg(fb + n * Fn + f) : 0.0f;
        fs[f * FB_LD + n] = __float2half_rn(w);
    }
    // vnr tile: raw fp16 copy, zero pad past T and past Fn
    const size_t vb = (size_t)b * Fn * Tn;
    for (int i = tid; i < FPAD * (TTILE / 8); i += 256) {
        int f = i >> 4;                      // TTILE/8 == 16
        int c = (i & 15) * 8;
        int t = t0 + c;
        uint4 r = make_uint4(0u, 0u, 0u, 0u);
        if (f < Fn && t < Tn)
            r = *reinterpret_cast<const uint4*>(g_vnr + vb + (size_t)f * Tn + t);
        *reinterpret_cast<uint4*>(vs + f * TTILE + c) = r;
    }
    __syncthreads();

    const int tn = tid >> 5;    // band octet 0..7
    const int tt = tid & 31;    // t quad 0..31

    ull acc[4][4];              // [n-pair p][t q] packed f32x2 (n=2p, n=2p+1)
    #pragma unroll
    for (int p = 0; p < 4; ++p)
        #pragma unroll
        for (int q = 0; q < 4; ++q) acc[p][q] = f2pack(0.f, 0.f);

    const __half* vrow = vs + tt * 4;
    const __half* frow = fs + tn * 8;

    for (int fo = 0; fo < FPAD; fo += 16) {
        __half2 ah[4][4];
        #pragma unroll
        for (int p = 0; p < 4; ++p)
            #pragma unroll
            for (int q = 0; q < 4; ++q) ah[p][q] = __floats2half2_rn(0.f, 0.f);

        #pragma unroll
        for (int fi = 0; fi < 16; ++fi) {
            int f = fo + fi;
            // v: 4 t-values (2 half2)
            uint2 vr = *reinterpret_cast<const uint2*>(vrow + f * TTILE);
            __half2 va = *reinterpret_cast<__half2*>(&vr.x);   // (t0, t1)
            __half2 vc = *reinterpret_cast<__half2*>(&vr.y);   // (t2, t3)
            __half2 vd0 = __half2half2(__low2half(va));
            __half2 vd1 = __half2half2(__high2half(va));
            __half2 vd2 = __half2half2(__low2half(vc));
            __half2 vd3 = __half2half2(__high2half(vc));
            // fb: 8 band values (4 half2 pairs) in one LDS.128 (warp broadcast)
            uint4 wr = *reinterpret_cast<const uint4*>(frow + f * FB_LD);
            __half2 w0 = *reinterpret_cast<__half2*>(&wr.x);
            __half2 w1 = *reinterpret_cast<__half2*>(&wr.y);
            __half2 w2 = *reinterpret_cast<__half2*>(&wr.z);
            __half2 w3 = *reinterpret_cast<__half2*>(&wr.w);

            ah[0][0] = __hfma2(vd0, w0, ah[0][0]);
            ah[0][1] = __hfma2(vd1, w0, ah[0][1]);
            ah[0][2] = __hfma2(vd2, w0, ah[0][2]);
            ah[0][3] = __hfma2(vd3, w0, ah[0][3]);
            ah[1][0] = __hfma2(vd0, w1, ah[1][0]);
            ah[1][1] = __hfma2(vd1, w1, ah[1][1]);
            ah[1][2] = __hfma2(vd2, w1, ah[1][2]);
            ah[1][3] = __hfma2(vd3, w1, ah[1][3]);
            ah[2][0] = __hfma2(vd0, w2, ah[2][0]);
            ah[2][1] = __hfma2(vd1, w2, ah[2][1]);
            ah[2][2] = __hfma2(vd2, w2, ah[2][2]);
            ah[2][3] = __hfma2(vd3, w2, ah[2][3]);
            ah[3][0] = __hfma2(vd0, w3, ah[3][0]);
            ah[3][1] = __hfma2(vd1, w3, ah[3][1]);
            ah[3][2] = __hfma2(vd2, w3, ah[3][2]);
            ah[3][3] = __hfma2(vd3, w3, ah[3][3]);
        }

        // flush fp16 partials into f32x2 master accumulators
        #pragma unroll
        for (int p = 0; p < 4; ++p)
            #pragma unroll
            for (int q = 0; q < 4; ++q) {
                float2 fv = __half22float2(ah[p][q]);
                acc[p][q] = f2add(acc[p][q], f2pack(fv.x, fv.y));
            }
    }

    // epilogue: tanh(sum) (/10 folded into scratch)
    if (t0 + tt * 4 < Tn) {
        #pragma unroll
        for (int p = 0; p < 4; ++p) {
            float s0[4], s1[4];
            #pragma unroll
            for (int q = 0; q < 4; ++q) f2unpack(acc[p][q], s0[q], s1[q]);
            int n0 = tn * 8 + 2 * p;
            size_t ob = ((size_t)b * NBn + n0) * Tn + t0 + tt * 4;
            float4 o0, o1;
            o0.x = tanhf(s0[0]); o0.y = tanhf(s0[1]);
            o0.z = tanhf(s0[2]); o0.w = tanhf(s0[3]);
            o1.x = tanhf(s1[0]); o1.y = tanhf(s1[1]);
            o1.z = tanhf(s1[2]); o1.w = tanhf(s1[3]);
            *reinterpret_cast<float4*>(out + ob)      = o0;
            *reinterpret_cast<float4*>(out + ob + Tn) = o1;
        }
    }
}

// ============================================================
extern "C" void kernel_launch(void* const* d_in, const int* in_sizes, int n_in,
                              void* d_out, int out_size)
{
    const float* mag = (const float*)d_in[0];
    const float* fb  = (const float*)d_in[1];
    const float* ns  = (const float*)d_in[2];
    const float* rr  = (const float*)d_in[3];
    const float* rf  = (const float*)d_in[4];
    float* out = (float*)d_out;

    cudaFuncSetAttribute(band_kernel, cudaFuncAttributeMaxDynamicSharedMemorySize, SMEM2);

    int nthreads = Bn * Fn * NCH;
    scan_kernel<<<(nthreads + 255) / 256, 256>>>(mag, ns, rr, rf);

    dim3 grid((Tn + TTILE - 1) / TTILE, Bn);
    band_kernel<<<grid, 256, SMEM2>>>(fb, out);
}

// round 5
// speedup vs baseline: 1.8246x; 1.8246x over previous
#include <cuda_runtime.h>
#include <cuda_fp16.h>
#include <cstdint>

#define Bn 16
#define Fn 257
#define FPAD 272          // K padded to 17*16
#define Tn 8000
#define NBn 64
#define CHUNK 400
#define NCH 20
#define WARM 256
#define TTILE 128
#define KSTEPS 17

#define AST 136           // A smem stride (halves): 128 + 8 pad
#define BST 280           // B smem stride (halves): 272 + 8 pad
#define OST 132           // out-stage stride (floats): 128 + 4 pad
#define A_BYTES (FPAD * AST * 2)            // 73984
#define B_BYTES (NBn * BST * 2)             // 35840
#define SMEM_TOTAL (A_BYTES + B_BYTES)      // 109824

// 65.8 MB fp16 scratch: g_vnr[b][f][t] = 0.1 * vnr  (t-contiguous)
__device__ __align__(128) __half g_vnr[(size_t)Bn * Fn * Tn];

struct __align__(8) H4 { __half2 a, b; };

__device__ __forceinline__ uint32_t smem_u32(const void* p) {
    uint32_t a;
    asm("{ .reg .u64 t; cvta.to.shared.u64 t, %1; cvt.u32.u64 %0, t; }" : "=r"(a) : "l"(p));
    return a;
}
__device__ __forceinline__ void ldsm_x4_t(uint32_t a[4], uint32_t addr) {
    asm volatile("ldmatrix.sync.aligned.m8n8.x4.trans.shared.b16 {%0,%1,%2,%3}, [%4];"
        : "=r"(a[0]), "=r"(a[1]), "=r"(a[2]), "=r"(a[3]) : "r"(addr));
}
__device__ __forceinline__ void ldsm_x4(uint32_t a[4], uint32_t addr) {
    asm volatile("ldmatrix.sync.aligned.m8n8.x4.shared.b16 {%0,%1,%2,%3}, [%4];"
        : "=r"(a[0]), "=r"(a[1]), "=r"(a[2]), "=r"(a[3]) : "r"(addr));
}
__device__ __forceinline__ void mma16816(float d[4], const uint32_t a[4], uint32_t b0, uint32_t b1) {
    asm volatile("mma.sync.aligned.m16n8k16.row.col.f32.f16.f16.f32 "
        "{%0,%1,%2,%3}, {%4,%5,%6,%7}, {%8,%9}, {%0,%1,%2,%3};"
        : "+f"(d[0]), "+f"(d[1]), "+f"(d[2]), "+f"(d[3])
        : "r"(a[0]), "r"(a[1]), "r"(a[2]), "r"(a[3]), "r"(b0), "r"(b1));
}
__device__ __forceinline__ float tanh_fast(float x) {
    float y; asm("tanh.approx.f32 %0, %1;" : "=f"(y) : "f"(x)); return y;
}

// ---------------- branch-free contractive EMA step ----------------
__device__ __forceinline__ float nf_step(float x, float nf, float rise, float fall, float fl) {
    float d  = x - nf;
    float cr = fmaf(rise, d, nf);
    float cf = fmaf(fall, d, nf);
    return fmaxf(fmaxf(cr, cf), fl);
}

// ============================================================
// K1: chunked noise-floor scan -> fp16 scratch [b][f][t] (0.1 * vnr)
// (round-2 proven version)
// ============================================================
__global__ __launch_bounds__(256) void scan_kernel(
    const float* __restrict__ mag,
    const float* __restrict__ p_ns,
    const float* __restrict__ p_rr,
    const float* __restrict__ p_rf)
{
    int tid = blockIdx.x * 256 + threadIdx.x;
    if (tid >= Bn * Fn * NCH) return;
    int chunk = tid % NCH;
    int chain = tid / NCH;

    float rise = 1.0f / (1.0f + expf(-__ldg(p_rr)));
    float fall = 1.0f / (1.0f + expf(-__ldg(p_rf)));
    float ns   = fabsf(__ldg(p_ns));

    size_t base = (size_t)chain * Tn;
    const float4* gm = reinterpret_cast<const float4*>(mag + base);
    H4* gv = reinterpret_cast<H4*>(g_vnr + base);

    float mn = 3.4e38f;
    #pragma unroll
    for (int i = 0; i < 20; ++i) mn = fminf(mn, __ldg(mag + base + i));
    mn = fmaxf(mn, 1e-5f);
    const float fl = 0.5f * mn;
    float nf = mn;

    int t0 = chunk * CHUNK;
    int tw = (chunk == 0) ? 0 : (t0 - WARM);

    for (int q = (tw >> 2); q < (t0 >> 2); ++q) {
        float4 v = gm[q];
        nf = nf_step(v.x, nf, rise, fall, fl);
        nf = nf_step(v.y, nf, rise, fall, fl);
        nf = nf_step(v.z, nf, rise, fall, fl);
        nf = nf_step(v.w, nf, rise, fall, fl);
    }

    const int q0 = t0 >> 2;
    float4 b0 = gm[q0], b1 = gm[q0 + 1], b2 = gm[q0 + 2], b3 = gm[q0 + 3];

    #define EMIT4(c, idx) { \
        float o0, o1, o2, o3; \
        nf = nf_step(c.x, nf, rise, fall, fl); o0 = __fdividef(c.x, fmaf(ns, nf, 1e-8f)) * 0.1f; \
        nf = nf_step(c.y, nf, rise, fall, fl); o1 = __fdividef(c.y, fmaf(ns, nf, 1e-8f)) * 0.1f; \
        nf = nf_step(c.z, nf, rise, fall, fl); o2 = __fdividef(c.z, fmaf(ns, nf, 1e-8f)) * 0.1f; \
        nf = nf_step(c.w, nf, rise, fall, fl); o3 = __fdividef(c.w, fmaf(ns, nf, 1e-8f)) * 0.1f; \
        H4 st; st.a = __floats2half2_rn(o0, o1); st.b = __floats2half2_rn(o2, o3); \
        gv[idx] = st; }

    for (int i = 0; i < CHUNK / 4; i += 4) {
        float4 c0 = b0, c1 = b1, c2 = b2, c3 = b3;
        if (i + 8 <= CHUNK / 4) {
            b0 = gm[q0 + i + 4]; b1 = gm[q0 + i + 5];
            b2 = gm[q0 + i + 6]; b3 = gm[q0 + i + 7];
        }
        EMIT4(c0, q0 + i);
        EMIT4(c1, q0 + i + 1);
        EMIT4(c2, q0 + i + 2);
        EMIT4(c3, q0 + i + 3);
    }
    #undef EMIT4
}

// ============================================================
// K2: HMMA band GEMM.  D[128 t][64 n] = A[128 t][272 f] x B[64 n][272 f]^T
// A smem [f][t] (K-major) -> ldmatrix.x4.trans ; B smem [n][f] -> ldmatrix.x4
// 8 warps: warp w owns m-tile (16 t), all 8 n-tiles, 17 k16-steps, f32 acc.
// ============================================================
extern __shared__ char k2_smem[];

__global__ __launch_bounds__(256, 2) void band_kernel(
    const float* __restrict__ fb, float* __restrict__ out)
{
    const int b   = blockIdx.y;
    const int t0  = blockIdx.x * TTILE;
    const int tid = threadIdx.x;
    const int wid = tid >> 5;
    const int lane = tid & 31;

    __half* As = reinterpret_cast<__half*>(k2_smem);             // [FPAD][AST]
    __half* Bs = reinterpret_cast<__half*>(k2_smem + A_BYTES);   // [NBn][BST]
    const uint32_t As_u = smem_u32(As);
    const uint32_t Bs_u = smem_u32(Bs);

    // ---- fill A: g_vnr[b][f][t0..t0+127] -> As[f][t] (zeros for pad) ----
    for (int i = tid; i < FPAD * 16; i += 256) {
        int f = i >> 4;
        int c = (i & 15);            // 8-t chunk
        int t = t0 + c * 8;
        uint4 v = make_uint4(0u, 0u, 0u, 0u);
        if (f < Fn && t + 8 <= Tn)
            v = *reinterpret_cast<const uint4*>(g_vnr + ((size_t)b * Fn + f) * Tn + t);
        *reinterpret_cast<uint4*>(As + f * AST + c * 8) = v;
    }
    // ---- fill B: fb fp32 [n][f] -> fp16 Bs[n][f] (zeros for f>=Fn) ----
    for (int i = tid; i < NBn * (BST / 8); i += 256) {
        int n  = i / (BST / 8);
        int f0 = (i % (BST / 8)) * 8;
        __half h[8];
        #pragma unroll
        for (int j = 0; j < 8; ++j) {
            int f = f0 + j;
            h[j] = (f < Fn) ? __float2half_rn(__ldg(fb + n * Fn + f)) : __float2half_rn(0.0f);
        }
        *reinterpret_cast<uint4*>(Bs + n * BST + f0) = *reinterpret_cast<uint4*>(h);
    }
    __syncthreads();

    // ---- per-lane ldmatrix base addresses ----
    const int m0 = wid * 16;
    const int krow = (lane & 7) + ((lane >> 4) << 3);        // 0..15
    const int msel = ((lane >> 3) & 1) * 8;
    const uint32_t a_addr0 = As_u + (uint32_t)((krow * AST + m0 + msel) * 2);

    const int nrow = (lane & 7) + ((lane >> 4) << 3);        // 0..15 within n-pair
    const int ksel = ((lane >> 3) & 1) * 8;
    uint32_t b_addr0[4];
    #pragma unroll
    for (int j2 = 0; j2 < 4; ++j2)
        b_addr0[j2] = Bs_u + (uint32_t)(((j2 * 16 + nrow) * BST + ksel) * 2);

    float d[8][4];
    #pragma unroll
    for (int j = 0; j < 8; ++j)
        #pragma unroll
        for (int q = 0; q < 4; ++q) d[j][q] = 0.0f;

    for (int ks = 0; ks < KSTEPS; ++ks) {
        uint32_t a[4];
        ldsm_x4_t(a, a_addr0 + (uint32_t)(ks * 16 * AST * 2));
        #pragma unroll
        for (int j2 = 0; j2 < 4; ++j2) {
            uint32_t bb[4];
            ldsm_x4(bb, b_addr0[j2] + (uint32_t)(ks * 32));
            mma16816(d[j2 * 2],     a, bb[0], bb[1]);
            mma16816(d[j2 * 2 + 1], a, bb[2], bb[3]);
        }
    }

    // ---- stage D to smem [n][t] (overlaps A region) ----
    __syncthreads();
    float* stg = reinterpret_cast<float*>(k2_smem);          // [NBn][OST]
    const int g  = lane >> 2;
    const int tp = lane & 3;
    #pragma unroll
    for (int j = 0; j < 8; ++j) {
        int n = j * 8 + 2 * tp;
        int t = m0 + g;
        stg[n * OST + t]           = d[j][0];
        stg[(n + 1) * OST + t]     = d[j][1];
        stg[n * OST + t + 8]       = d[j][2];
        stg[(n + 1) * OST + t + 8] = d[j][3];
    }
    __syncthreads();

    // ---- tanh + coalesced float4 store ----
    const int tmax = Tn - t0;                                // 128 or 64 (last block)
    float* ob = out + (size_t)b * NBn * Tn + t0;
    #pragma unroll
    for (int it = 0; it < 8; ++it) {
        int idx = tid + it * 256;
        int n = idx >> 5;
        int c = (idx & 31) * 4;
        if (c < tmax) {
            float4 v = *reinterpret_cast<float4*>(stg + n * OST + c);
            v.x = tanh_fast(v.x); v.y = tanh_fast(v.y);
            v.z = tanh_fast(v.z); v.w = tanh_fast(v.w);
            *reinterpret_cast<float4*>(ob + (size_t)n * Tn + c) = v;
        }
    }
}

// ============================================================
extern "C" void kernel_launch(void* const* d_in, const int* in_sizes, int n_in,
                              void* d_out, int out_size)
{
    const float* mag = (const float*)d_in[0];
    const float* fb  = (const float*)d_in[1];
    const float* ns  = (const float*)d_in[2];
    const float* rr  = (const float*)d_in[3];
    const float* rf  = (const float*)d_in[4];
    float* out = (float*)d_out;

    cudaFuncSetAttribute(band_kernel, cudaFuncAttributeMaxDynamicSharedMemorySize, SMEM_TOTAL);

    int nthreads = Bn * Fn * NCH;
    scan_kernel<<<(nthreads + 255) / 256, 256>>>(mag, ns, rr, rf);

    dim3 grid((Tn + TTILE - 1) / TTILE, Bn);   // 63 x 16
    band_kernel<<<grid, 256, SMEM_TOTAL>>>(fb, out);
}